// round 12
// baseline (speedup 1.0000x reference)
#include <cuda_runtime.h>
#include <cuda_bf16.h>
#include <mma.h>
#include <math.h>
#include <stdint.h>

using namespace nvcuda;

#define BB 4
#define LL 1024
#define DD 1024
#define NH 16
#define DK 64
#define DV 64
#define LN_EPS 1e-5f

// ---------------------------------------------------------------------------
// Scratch (allocation-free rule: __device__ globals)
// ---------------------------------------------------------------------------
__device__ float g_Qp[BB*LL*DD];
__device__ float g_Kp[BB*LL*DD];
__device__ float g_Vp[BB*LL*DD];
__device__ float g_ctx[BB*LL*DD];
__device__ float g_x2[BB*LL*DD];

// bf16 split operands: act slots {0:q,1:k,2:v,3:ctx}, W slots {0:wq,1:wk,2:wv,3:fcw}
#define SA (BB*LL*DD)
#define SW (DD*DD)
__device__ __nv_bfloat16 g_act_hi[4*SA];
__device__ __nv_bfloat16 g_act_lo[4*SA];
__device__ __nv_bfloat16 g_w_hi[4*SW];
__device__ __nv_bfloat16 g_w_lo[4*SW];

// ---------------------------------------------------------------------------
// fp32 -> (bf16 hi, bf16 lo) split conversion. n4 = elements/4.
// ---------------------------------------------------------------------------
__global__ __launch_bounds__(256)
void cvt_split_kernel(const float* __restrict__ src, __nv_bfloat16* __restrict__ hi,
                      __nv_bfloat16* __restrict__ lo, int n4)
{
    int i = blockIdx.x * blockDim.x + threadIdx.x;
    if (i >= n4) return;
    float4 v = *(const float4*)(src + (size_t)i * 4);
    __nv_bfloat16 h0 = __float2bfloat16(v.x);
    __nv_bfloat16 h1 = __float2bfloat16(v.y);
    __nv_bfloat16 h2 = __float2bfloat16(v.z);
    __nv_bfloat16 h3 = __float2bfloat16(v.w);
    __nv_bfloat16 l0 = __float2bfloat16(v.x - __bfloat162float(h0));
    __nv_bfloat16 l1 = __float2bfloat16(v.y - __bfloat162float(h1));
    __nv_bfloat16 l2 = __float2bfloat16(v.z - __bfloat162float(h2));
    __nv_bfloat16 l3 = __float2bfloat16(v.w - __bfloat162float(h3));
    ushort4 hp = make_ushort4(__bfloat16_as_ushort(h0), __bfloat16_as_ushort(h1),
                              __bfloat16_as_ushort(h2), __bfloat16_as_ushort(h3));
    ushort4 lp = make_ushort4(__bfloat16_as_ushort(l0), __bfloat16_as_ushort(l1),
                              __bfloat16_as_ushort(l2), __bfloat16_as_ushort(l3));
    *(ushort4*)(hi + (size_t)i * 4) = hp;
    *(ushort4*)(lo + (size_t)i * 4) = lp;
}

// ---------------------------------------------------------------------------
// wmma bf16 3x-split GEMM: C[M,N] = A[M,K] @ W[N,K]^T + bias[N]
// D = Ahi*Whi + Ahi*Wlo + Alo*Whi  (fp32 accum; dropped lo*lo term ~2^-18)
// CTA tile 128x128, 8 warps (2x4), warp tile 64x32, K-chunk 32.
// ---------------------------------------------------------------------------
#define KC 32
#define AST 40   // smem row stride (elements); 80B rows; frag rows (mult of 16) stay 32B-aligned

__global__ __launch_bounds__(256)
void wgemm128(const __nv_bfloat16* __restrict__ ahi_base, const __nv_bfloat16* __restrict__ alo_base,
              const __nv_bfloat16* __restrict__ whi_base, const __nv_bfloat16* __restrict__ wlo_base,
              const float* __restrict__ b0, const float* __restrict__ b1, const float* __restrict__ b2,
              float* __restrict__ C0, float* __restrict__ C1, float* __restrict__ C2,
              int M, int N, int K, size_t strideA, size_t strideW)
{
    __shared__ __nv_bfloat16 sAh[128 * AST];
    __shared__ __nv_bfloat16 sAl[128 * AST];
    __shared__ __nv_bfloat16 sWh[128 * AST];
    __shared__ __nv_bfloat16 sWl[128 * AST];

    const int t   = threadIdx.x;
    const int wid = t >> 5;
    const int z   = blockIdx.z;
    const int bm  = blockIdx.y * 128;
    const int bn  = blockIdx.x * 128;
    const int wm  = wid >> 2;
    const int wn  = wid & 3;

    const __nv_bfloat16* Ah = ahi_base + (size_t)z * strideA;
    const __nv_bfloat16* Al = alo_base + (size_t)z * strideA;
    const __nv_bfloat16* Wh = whi_base + (size_t)z * strideW;
    const __nv_bfloat16* Wl = wlo_base + (size_t)z * strideW;
    const float* bias = (z == 0) ? b0 : (z == 1) ? b1 : b2;
    float*       C    = (z == 0) ? C0 : (z == 1) ? C1 : C2;

    // ---- bias -> accumulator fragments (reuse sAh region as fp32 tile) ----
    wmma::fragment<wmma::accumulator, 16, 16, 16, float> acc[4][2];
    {
        float* sBias = (float*)sAh;      // 16 x 128 fp32 broadcast tile
        #pragma unroll
        for (int e = 0; e < 8; e++) {
            int idx = t * 8 + e;
            int col = idx & 127;
            sBias[idx] = bias[bn + col];
        }
        __syncthreads();
        #pragma unroll
        for (int j = 0; j < 2; j++) {
            wmma::fragment<wmma::accumulator, 16, 16, 16, float> bfr;
            wmma::load_matrix_sync(bfr, &sBias[wn * 32 + j * 16], 128, wmma::mem_row_major);
            #pragma unroll
            for (int i = 0; i < 4; i++) acc[i][j] = bfr;
        }
        __syncthreads();
    }

    const int r0 = t >> 2,         c0 = t & 3;
    const int r1 = (t + 256) >> 2, c1 = (t + 256) & 3;

    uint4 pAh0, pAh1, pAl0, pAl1, pWh0, pWh1, pWl0, pWl1;
    {
        pAh0 = *(const uint4*)(Ah + (size_t)(bm + r0) * K + c0 * 8);
        pAh1 = *(const uint4*)(Ah + (size_t)(bm + r1) * K + c1 * 8);
        pAl0 = *(const uint4*)(Al + (size_t)(bm + r0) * K + c0 * 8);
        pAl1 = *(const uint4*)(Al + (size_t)(bm + r1) * K + c1 * 8);
        pWh0 = *(const uint4*)(Wh + (size_t)(bn + r0) * K + c0 * 8);
        pWh1 = *(const uint4*)(Wh + (size_t)(bn + r1) * K + c1 * 8);
        pWl0 = *(const uint4*)(Wl + (size_t)(bn + r0) * K + c0 * 8);
        pWl1 = *(const uint4*)(Wl + (size_t)(bn + r1) * K + c1 * 8);
    }

    for (int kofs = 0; kofs < K; kofs += KC) {
        *(uint4*)(sAh + r0 * AST + c0 * 8) = pAh0;
        *(uint4*)(sAh + r1 * AST + c1 * 8) = pAh1;
        *(uint4*)(sAl + r0 * AST + c0 * 8) = pAl0;
        *(uint4*)(sAl + r1 * AST + c1 * 8) = pAl1;
        *(uint4*)(sWh + r0 * AST + c0 * 8) = pWh0;
        *(uint4*)(sWh + r1 * AST + c1 * 8) = pWh1;
        *(uint4*)(sWl + r0 * AST + c0 * 8) = pWl0;
        *(uint4*)(sWl + r1 * AST + c1 * 8) = pWl1;
        __syncthreads();

        if (kofs + KC < K) {
            const int kn = kofs + KC;
            pAh0 = *(const uint4*)(Ah + (size_t)(bm + r0) * K + kn + c0 * 8);
            pAh1 = *(const uint4*)(Ah + (size_t)(bm + r1) * K + kn + c1 * 8);
            pAl0 = *(const uint4*)(Al + (size_t)(bm + r0) * K + kn + c0 * 8);
            pAl1 = *(const uint4*)(Al + (size_t)(bm + r1) * K + kn + c1 * 8);
            pWh0 = *(const uint4*)(Wh + (size_t)(bn + r0) * K + kn + c0 * 8);
            pWh1 = *(const uint4*)(Wh + (size_t)(bn + r1) * K + kn + c1 * 8);
            pWl0 = *(const uint4*)(Wl + (size_t)(bn + r0) * K + kn + c0 * 8);
            pWl1 = *(const uint4*)(Wl + (size_t)(bn + r1) * K + kn + c1 * 8);
        }

        #pragma unroll
        for (int ks = 0; ks < KC / 16; ks++) {
            wmma::fragment<wmma::matrix_b, 16, 16, 16, __nv_bfloat16, wmma::col_major> b_hi[2], b_lo[2];
            #pragma unroll
            for (int j = 0; j < 2; j++) {
                wmma::load_matrix_sync(b_hi[j], &sWh[(wn * 32 + j * 16) * AST + ks * 16], AST);
                wmma::load_matrix_sync(b_lo[j], &sWl[(wn * 32 + j * 16) * AST + ks * 16], AST);
            }
            #pragma unroll
            for (int i = 0; i < 4; i++) {
                wmma::fragment<wmma::matrix_a, 16, 16, 16, __nv_bfloat16, wmma::row_major> a_hi, a_lo;
                wmma::load_matrix_sync(a_hi, &sAh[(wm * 64 + i * 16) * AST + ks * 16], AST);
                wmma::load_matrix_sync(a_lo, &sAl[(wm * 64 + i * 16) * AST + ks * 16], AST);
                #pragma unroll
                for (int j = 0; j < 2; j++) {
                    wmma::mma_sync(acc[i][j], a_hi, b_hi[j], acc[i][j]);
                    wmma::mma_sync(acc[i][j], a_hi, b_lo[j], acc[i][j]);
                    wmma::mma_sync(acc[i][j], a_lo, b_hi[j], acc[i][j]);
                }
            }
        }
        __syncthreads();
    }

    #pragma unroll
    for (int i = 0; i < 4; i++)
        #pragma unroll
        for (int j = 0; j < 2; j++) {
            float* dst = C + (size_t)(bm + wm * 64 + i * 16) * N + bn + wn * 32 + j * 16;
            wmma::store_matrix_sync(dst, acc[i][j], N, wmma::mem_row_major);
        }
}

// ---------------------------------------------------------------------------
// Fused attention: 32 query rows x 1024 keys per block.
// Q/K smem stride 68 (16B-aligned rows, conflict-free LDS.128) -> vectorized
// phase-1. QK^T/8 + key mask -> softmax (branch-free) -> write attn once ->
// P@V -> ctx.
// ---------------------------------------------------------------------------
#define QT 32
#define QKS 68           // Q/K smem row stride: 68*4B=272B, 16B-aligned; 17 mod 8 = 1 -> conflict-free
#define PS_STRIDE 1032

__global__ __launch_bounds__(256)
void fused_attn_kernel(const float* __restrict__ Qp, const float* __restrict__ Kp,
                       const float* __restrict__ Vp, const int* __restrict__ seq_len,
                       float* __restrict__ attn, float* __restrict__ ctx)
{
    extern __shared__ float sm[];
    float* Qs  = sm;                  // [32][QKS]
    float* KVs = Qs + QT * QKS;       // K: [128][QKS] / V-phase: [128][64] packed
    float* Ps  = KVs + 128 * QKS;     // [32][PS_STRIDE]

    const int t  = threadIdx.x;
    const int q0 = blockIdx.x * QT;
    const int bh = blockIdx.y;
    const int b  = bh / NH;
    const int h  = bh % NH;
    const int sl = seq_len[b];

    const float* Qb = Qp + (size_t)b * LL * DD + h * DK;
    const float* Kb = Kp + (size_t)b * LL * DD + h * DK;
    const float* Vb = Vp + (size_t)b * LL * DD + h * DV;

    const int kr_base = t >> 4;       // row 0..15 (+16 per chunk)
    const int kc4     = t & 15;       // float4 col 0..15

    // ---- load Q tile [32][64] -> stride-QKS smem (float4 stores, aligned) ----
    #pragma unroll
    for (int m = 0; m < 2; m++) {
        int fi = m * 256 + t;         // 0..511
        int r  = fi >> 4;             // 0..31
        int c4 = fi & 15;             // 0..15
        float4 v = *(const float4*)(Qb + (size_t)(q0 + r) * DD + c4 * 4);
        *(float4*)(Qs + r * QKS + c4 * 4) = v;
    }

    const int tx = t & 31;
    const int ty = t >> 5;

    float4 pf[8];
    #pragma unroll
    for (int m = 0; m < 8; m++)
        pf[m] = *(const float4*)(Kb + (size_t)(kr_base + m * 16) * DD + kc4 * 4);

    for (int kt = 0; kt < LL; kt += 128) {
        __syncthreads();
        #pragma unroll
        for (int m = 0; m < 8; m++)
            *(float4*)(KVs + (kr_base + m * 16) * QKS + kc4 * 4) = pf[m];
        if (kt + 128 < LL) {
            #pragma unroll
            for (int m = 0; m < 8; m++)
                pf[m] = *(const float4*)(Kb + (size_t)(kt + 128 + kr_base + m * 16) * DD + kc4 * 4);
        }
        __syncthreads();

        float acc[4][4] = {};
        #pragma unroll
        for (int d4 = 0; d4 < 16; d4++) {         // 4 d's per iter, vectorized
            float4 qv[4], wv[4];
            #pragma unroll
            for (int i = 0; i < 4; i++)
                qv[i] = *(const float4*)(Qs + (i * 8 + ty) * QKS + d4 * 4);   // broadcast
            #pragma unroll
            for (int j = 0; j < 4; j++)
                wv[j] = *(const float4*)(KVs + (j * 32 + tx) * QKS + d4 * 4); // conflict-free
            #pragma unroll
            for (int i = 0; i < 4; i++)
                #pragma unroll
                for (int j = 0; j < 4; j++) {
                    acc[i][j] = fmaf(qv[i].x, wv[j].x, acc[i][j]);
                    acc[i][j] = fmaf(qv[i].y, wv[j].y, acc[i][j]);
                    acc[i][j] = fmaf(qv[i].z, wv[j].z, acc[i][j]);
                    acc[i][j] = fmaf(qv[i].w, wv[j].w, acc[i][j]);
                }
        }

        #pragma unroll
        for (int i = 0; i < 4; i++) {
            int qq = i * 8 + ty;
            #pragma unroll
            for (int j = 0; j < 4; j++) {
                int kk = kt + j * 32 + tx;
                float v = acc[i][j] * 0.125f;
                if (kk >= sl) v = -INFINITY;
                Ps[qq * PS_STRIDE + kk] = v;
            }
        }
    }
    __syncthreads();

    // ---- Phase 2: softmax, branch-free (shuffles uniform across warp) ----
    {
        const int g    = t >> 3;              // row 0..31
        const int su   = t & 7;
        const bool live = (q0 + g) < sl;      // dead query rows -> zeros at store
        float* row = Ps + g * PS_STRIDE;

        float mx = -INFINITY;
        #pragma unroll 16
        for (int m = 0; m < 128; m++) mx = fmaxf(mx, row[su + m * 8]);
        #pragma unroll
        for (int o = 4; o > 0; o >>= 1) mx = fmaxf(mx, __shfl_xor_sync(0xffffffffu, mx, o, 8));

        float s = 0.0f;
        #pragma unroll 16
        for (int m = 0; m < 128; m++) {
            float ev = __expf(row[su + m * 8] - mx);   // exp(-inf)=0 covers key mask
            row[su + m * 8] = ev;
            s += ev;
        }
        #pragma unroll
        for (int o = 4; o > 0; o >>= 1) s += __shfl_xor_sync(0xffffffffu, s, o, 8);

        const float inv = live ? (1.0f / s) : 0.0f;    // sl>=1 => s>0 for live rows
        #pragma unroll 16
        for (int m = 0; m < 128; m++) row[su + m * 8] *= inv;
    }
    __syncthreads();

    // ---- Phase 3: write attention probs to gmem (single mandatory pass) ----
    {
        float* ab = attn + ((size_t)(h * BB + b)) * LL * LL + (size_t)q0 * LL;
        #pragma unroll
        for (int m = 0; m < 32; m++) {
            int fi = m * 256 + t;
            int r  = fi >> 8;
            int c4 = fi & 255;
            const float* src = Ps + r * PS_STRIDE + c4 * 4;
            *(float4*)(ab + (size_t)r * LL + c4 * 4) =
                make_float4(src[0], src[1], src[2], src[3]);
        }
    }

    // ---- Phase 4: O = P @ V from smem (P as float4, V broadcast) ----
    const int vx = t & 15;
    const int vq = t >> 4;
    float acc2[2][4] = {};

    #pragma unroll
    for (int m = 0; m < 8; m++)
        pf[m] = *(const float4*)(Vb + (size_t)(kr_base + m * 16) * DD + kc4 * 4);

    for (int kt = 0; kt < LL; kt += 128) {
        __syncthreads();
        #pragma unroll
        for (int m = 0; m < 8; m++)
            *(float4*)(KVs + (kr_base + m * 16) * 64 + kc4 * 4) = pf[m];
        if (kt + 128 < LL) {
            #pragma unroll
            for (int m = 0; m < 8; m++)
                pf[m] = *(const float4*)(Vb + (size_t)(kt + 128 + kr_base + m * 16) * DD + kc4 * 4);
        }
        __syncthreads();

        #pragma unroll 4
        for (int k4 = 0; k4 < 32; k4++) {
            float4 p0 = *(const float4*)&Ps[(vq)      * PS_STRIDE + kt + k4 * 4];
            float4 p1 = *(const float4*)&Ps[(16 + vq) * PS_STRIDE + kt + k4 * 4];
            const float* pa0 = &p0.x;
            const float* pa1 = &p1.x;
            #pragma unroll
            for (int u = 0; u < 4; u++) {
                float4 v4 = *(const float4*)(KVs + (k4 * 4 + u) * 64 + vx * 4);
                float a0 = pa0[u], a1 = pa1[u];
                acc2[0][0] = fmaf(a0, v4.x, acc2[0][0]);
                acc2[0][1] = fmaf(a0, v4.y, acc2[0][1]);
                acc2[0][2] = fmaf(a0, v4.z, acc2[0][2]);
                acc2[0][3] = fmaf(a0, v4.w, acc2[0][3]);
                acc2[1][0] = fmaf(a1, v4.x, acc2[1][0]);
                acc2[1][1] = fmaf(a1, v4.y, acc2[1][1]);
                acc2[1][2] = fmaf(a1, v4.z, acc2[1][2]);
                acc2[1][3] = fmaf(a1, v4.w, acc2[1][3]);
            }
        }
    }

    #pragma unroll
    for (int i = 0; i < 2; i++) {
        int qq = i * 16 + vq;
        *(float4*)(ctx + ((size_t)b * LL + q0 + qq) * DD + h * DV + vx * 4) =
            make_float4(acc2[i][0], acc2[i][1], acc2[i][2], acc2[i][3]);
    }
}

#define SMEM_FUSED ((QT*QKS + 128*QKS + QT*PS_STRIDE) * (int)sizeof(float))

// ---------------------------------------------------------------------------
__device__ __forceinline__ float block_reduce_sum(float v)
{
    __shared__ float sh[8];
    int lane = threadIdx.x & 31, w = threadIdx.x >> 5;
    #pragma unroll
    for (int o = 16; o > 0; o >>= 1) v += __shfl_xor_sync(0xffffffffu, v, o);
    if (lane == 0) sh[w] = v;
    __syncthreads();
    if (w == 0) {
        float x = (lane < 8) ? sh[lane] : 0.0f;
        #pragma unroll
        for (int o = 4; o > 0; o >>= 1) x += __shfl_xor_sync(0xffffffffu, x, o);
        if (lane == 0) sh[0] = x;
    }
    __syncthreads();
    float r = sh[0];
    __syncthreads();
    return r;
}

// ---------------------------------------------------------------------------
// LayerNorm per row, residual folded: out = LN(x + res).
// ---------------------------------------------------------------------------
__global__ __launch_bounds__(256)
void layernorm_kernel(const float* __restrict__ x, const float* __restrict__ res,
                      const float* __restrict__ gamma, const float* __restrict__ beta,
                      float* __restrict__ out)
{
    const int row = blockIdx.x;
    const float* xr = x   + (size_t)row * DD;
    const float* rr = res + (size_t)row * DD;
    const int t = threadIdx.x;

    float v[4], s = 0.0f;
    #pragma unroll
    for (int i = 0; i < 4; i++) {
        int c = t + i * 256;
        v[i] = xr[c] + rr[c];
        s += v[i];
    }
    s = block_reduce_sum(s);
    const float mu = s * (1.0f / DD);

    float s2 = 0.0f;
    #pragma unroll
    for (int i = 0; i < 4; i++) { float d = v[i] - mu; s2 += d * d; }
    s2 = block_reduce_sum(s2);
    const float inv = rsqrtf(s2 * (1.0f / DD) + LN_EPS);

    #pragma unroll
    for (int i = 0; i < 4; i++) {
        int c = t + i * 256;
        out[(size_t)row * DD + c] = (v[i] - mu) * inv * gamma[c] + beta[c];
    }
}

// ---------------------------------------------------------------------------
// Launch
// ---------------------------------------------------------------------------
extern "C" void kernel_launch(void* const* d_in, const int* in_sizes, int n_in,
                              void* d_out, int out_size)
{
    const float* q       = (const float*)d_in[0];
    const float* k       = (const float*)d_in[1];
    const float* v       = (const float*)d_in[2];
    const int*   seq_len = (const int*)  d_in[3];
    const float* w_qs    = (const float*)d_in[4];
    const float* b_qs    = (const float*)d_in[5];
    const float* w_ks    = (const float*)d_in[6];
    const float* b_ks    = (const float*)d_in[7];
    const float* w_vs    = (const float*)d_in[8];
    const float* b_vs    = (const float*)d_in[9];
    const float* fc_w    = (const float*)d_in[10];
    const float* fc_b    = (const float*)d_in[11];
    const float* ln_g    = (const float*)d_in[12];
    const float* ln_b    = (const float*)d_in[13];

    float* out  = (float*)d_out;
    float* attn = out + (size_t)BB * LL * DD;

    float *Qp, *Kp, *Vp, *ctx, *x2;
    __nv_bfloat16 *ahi, *alo, *whi, *wlo;
    cudaGetSymbolAddress((void**)&Qp,  g_Qp);
    cudaGetSymbolAddress((void**)&Kp,  g_Kp);
    cudaGetSymbolAddress((void**)&Vp,  g_Vp);
    cudaGetSymbolAddress((void**)&ctx, g_ctx);
    cudaGetSymbolAddress((void**)&x2,  g_x2);
    cudaGetSymbolAddress((void**)&ahi, g_act_hi);
    cudaGetSymbolAddress((void**)&alo, g_act_lo);
    cudaGetSymbolAddress((void**)&whi, g_w_hi);
    cudaGetSymbolAddress((void**)&wlo, g_w_lo);

    cudaFuncSetAttribute(fused_attn_kernel,
                         cudaFuncAttributeMaxDynamicSharedMemorySize, SMEM_FUSED);

    const int M = BB * LL;
    const int ACT4 = SA / 4;   // 1048576
    const int W4   = SW / 4;   // 262144

    // split-convert inputs + weights
    cvt_split_kernel<<<ACT4 / 256, 256>>>(q,    ahi + 0*(size_t)SA, alo + 0*(size_t)SA, ACT4);
    cvt_split_kernel<<<ACT4 / 256, 256>>>(k,    ahi + 1*(size_t)SA, alo + 1*(size_t)SA, ACT4);
    cvt_split_kernel<<<ACT4 / 256, 256>>>(v,    ahi + 2*(size_t)SA, alo + 2*(size_t)SA, ACT4);
    cvt_split_kernel<<<W4 / 256, 256>>>(w_qs, whi + 0*(size_t)SW, wlo + 0*(size_t)SW, W4);
    cvt_split_kernel<<<W4 / 256, 256>>>(w_ks, whi + 1*(size_t)SW, wlo + 1*(size_t)SW, W4);
    cvt_split_kernel<<<W4 / 256, 256>>>(w_vs, whi + 2*(size_t)SW, wlo + 2*(size_t)SW, W4);
    cvt_split_kernel<<<W4 / 256, 256>>>(fc_w, whi + 3*(size_t)SW, wlo + 3*(size_t)SW, W4);

    // QKV projections: wmma tensor cores, one launch via gridDim.z
    wgemm128<<<dim3(DD / 128, M / 128, 3), 256>>>(
        ahi, alo, whi, wlo, b_qs, b_ks, b_vs,
        Qp, Kp, Vp, M, DD, DD, (size_t)SA, (size_t)SW);

    fused_attn_kernel<<<dim3(LL / QT, BB * NH), 256, SMEM_FUSED>>>(
        Qp, Kp, Vp, seq_len, attn, ctx);

    // FC: convert ctx, wmma GEMM (bias only; residual folds into LN)
    cvt_split_kernel<<<ACT4 / 256, 256>>>(ctx, ahi + 3*(size_t)SA, alo + 3*(size_t)SA, ACT4);
    wgemm128<<<dim3(DD / 128, M / 128, 1), 256>>>(
        ahi + 3*(size_t)SA, alo + 3*(size_t)SA, whi + 3*(size_t)SW, wlo + 3*(size_t)SW,
        fc_b, fc_b, fc_b, x2, x2, x2, M, DD, DD, 0, 0);

    layernorm_kernel<<<M, 256>>>(x2, q, ln_g, ln_b, out);
}

// round 13
// speedup vs baseline: 1.2512x; 1.2512x over previous
#include <cuda_runtime.h>
#include <cuda_bf16.h>
#include <mma.h>
#include <math.h>
#include <stdint.h>

using namespace nvcuda;

#define BB 4
#define LL 1024
#define DD 1024
#define NH 16
#define DK 64
#define LN_EPS 1e-5f

#define SA (BB*LL*DD)
#define SW (DD*DD)

// ---------------------------------------------------------------------------
// Scratch (allocation-free rule: __device__ globals)
// ---------------------------------------------------------------------------
__device__ __nv_bfloat16 g_act_hi[3*SA];   // q,k,v inputs (GEMM A operands)
__device__ __nv_bfloat16 g_act_lo[3*SA];
__device__ __nv_bfloat16 g_w_hi[4*SW];     // wq,wk,wv,fcw
__device__ __nv_bfloat16 g_w_lo[4*SW];
__device__ __nv_bfloat16 g_proj_hi[3*SA];  // projected Q,K,V (wgemm epilogue)
__device__ __nv_bfloat16 g_proj_lo[3*SA];
__device__ __nv_bfloat16 g_ctx_hi[SA];     // attention context (attn epilogue)
__device__ __nv_bfloat16 g_ctx_lo[SA];
__device__ float g_x2[SA];                 // FC output fp32

// ---------------------------------------------------------------------------
// fp32 -> (bf16 hi, bf16 lo) split; up to 4 sources via gridDim.z.
// ---------------------------------------------------------------------------
__global__ __launch_bounds__(256)
void cvt_splitN(const float* __restrict__ s0, const float* __restrict__ s1,
                const float* __restrict__ s2, const float* __restrict__ s3,
                __nv_bfloat16* __restrict__ hi_base, __nv_bfloat16* __restrict__ lo_base,
                size_t stride, int n4)
{
    int i = blockIdx.x * blockDim.x + threadIdx.x;
    if (i >= n4) return;
    const int z = blockIdx.z;
    const float* src = (z == 0) ? s0 : (z == 1) ? s1 : (z == 2) ? s2 : s3;
    __nv_bfloat16* hi = hi_base + (size_t)z * stride;
    __nv_bfloat16* lo = lo_base + (size_t)z * stride;

    float4 v = *(const float4*)(src + (size_t)i * 4);
    __nv_bfloat16 h0 = __float2bfloat16(v.x);
    __nv_bfloat16 h1 = __float2bfloat16(v.y);
    __nv_bfloat16 h2 = __float2bfloat16(v.z);
    __nv_bfloat16 h3 = __float2bfloat16(v.w);
    __nv_bfloat16 l0 = __float2bfloat16(v.x - __bfloat162float(h0));
    __nv_bfloat16 l1 = __float2bfloat16(v.y - __bfloat162float(h1));
    __nv_bfloat16 l2 = __float2bfloat16(v.z - __bfloat162float(h2));
    __nv_bfloat16 l3 = __float2bfloat16(v.w - __bfloat162float(h3));
    *(ushort4*)(hi + (size_t)i * 4) = make_ushort4(
        __bfloat16_as_ushort(h0), __bfloat16_as_ushort(h1),
        __bfloat16_as_ushort(h2), __bfloat16_as_ushort(h3));
    *(ushort4*)(lo + (size_t)i * 4) = make_ushort4(
        __bfloat16_as_ushort(l0), __bfloat16_as_ushort(l1),
        __bfloat16_as_ushort(l2), __bfloat16_as_ushort(l3));
}

// ---------------------------------------------------------------------------
// wmma bf16 3x-split GEMM: C = A @ W^T + bias.
// MODE 0: output bf16 hi/lo (QKV projections). MODE 1: output fp32 (FC).
// CTA tile 128x128, 8 warps, warp tile 64x32, K-chunk 32. Validated R12.
// ---------------------------------------------------------------------------
#define KC 32
#define AST 40

template<int MODE>
__global__ __launch_bounds__(256)
void wgemm128(const __nv_bfloat16* __restrict__ ahi_base, const __nv_bfloat16* __restrict__ alo_base,
              const __nv_bfloat16* __restrict__ whi_base, const __nv_bfloat16* __restrict__ wlo_base,
              const float* __restrict__ b0, const float* __restrict__ b1, const float* __restrict__ b2,
              float* __restrict__ C0, float* __restrict__ C1, float* __restrict__ C2,
              __nv_bfloat16* __restrict__ H0, __nv_bfloat16* __restrict__ H1, __nv_bfloat16* __restrict__ H2,
              __nv_bfloat16* __restrict__ Lo0, __nv_bfloat16* __restrict__ Lo1, __nv_bfloat16* __restrict__ Lo2,
              int M, int N, int K, size_t strideA, size_t strideW)
{
    __shared__ __nv_bfloat16 sAh[128 * AST];
    __shared__ __nv_bfloat16 sAl[128 * AST];
    __shared__ __nv_bfloat16 sWh[128 * AST];
    __shared__ __nv_bfloat16 sWl[128 * AST];

    const int t    = threadIdx.x;
    const int wid  = t >> 5;
    const int lane = t & 31;
    const int z    = blockIdx.z;
    const int bm   = blockIdx.y * 128;
    const int bn   = blockIdx.x * 128;
    const int wm   = wid >> 2;
    const int wn   = wid & 3;

    const __nv_bfloat16* Ah = ahi_base + (size_t)z * strideA;
    const __nv_bfloat16* Al = alo_base + (size_t)z * strideA;
    const __nv_bfloat16* Wh = whi_base + (size_t)z * strideW;
    const __nv_bfloat16* Wl = wlo_base + (size_t)z * strideW;
    const float* bias = (z == 0) ? b0 : (z == 1) ? b1 : b2;

    // ---- bias -> accumulator fragments (validated R12) ----
    wmma::fragment<wmma::accumulator, 16, 16, 16, float> acc[4][2];
    {
        float* sBias = (float*)sAh;
        #pragma unroll
        for (int e = 0; e < 8; e++) {
            int idx = t * 8 + e;
            sBias[idx] = bias[bn + (idx & 127)];
        }
        __syncthreads();
        #pragma unroll
        for (int j = 0; j < 2; j++) {
            wmma::fragment<wmma::accumulator, 16, 16, 16, float> bfr;
            wmma::load_matrix_sync(bfr, &sBias[wn * 32 + j * 16], 128, wmma::mem_row_major);
            #pragma unroll
            for (int i = 0; i < 4; i++) acc[i][j] = bfr;
        }
        __syncthreads();
    }

    const int r0 = t >> 2,         c0 = t & 3;
    const int r1 = (t + 256) >> 2, c1 = (t + 256) & 3;

    uint4 pAh0, pAh1, pAl0, pAl1, pWh0, pWh1, pWl0, pWl1;
    pAh0 = *(const uint4*)(Ah + (size_t)(bm + r0) * K + c0 * 8);
    pAh1 = *(const uint4*)(Ah + (size_t)(bm + r1) * K + c1 * 8);
    pAl0 = *(const uint4*)(Al + (size_t)(bm + r0) * K + c0 * 8);
    pAl1 = *(const uint4*)(Al + (size_t)(bm + r1) * K + c1 * 8);
    pWh0 = *(const uint4*)(Wh + (size_t)(bn + r0) * K + c0 * 8);
    pWh1 = *(const uint4*)(Wh + (size_t)(bn + r1) * K + c1 * 8);
    pWl0 = *(const uint4*)(Wl + (size_t)(bn + r0) * K + c0 * 8);
    pWl1 = *(const uint4*)(Wl + (size_t)(bn + r1) * K + c1 * 8);

    for (int kofs = 0; kofs < K; kofs += KC) {
        *(uint4*)(sAh + r0 * AST + c0 * 8) = pAh0;
        *(uint4*)(sAh + r1 * AST + c1 * 8) = pAh1;
        *(uint4*)(sAl + r0 * AST + c0 * 8) = pAl0;
        *(uint4*)(sAl + r1 * AST + c1 * 8) = pAl1;
        *(uint4*)(sWh + r0 * AST + c0 * 8) = pWh0;
        *(uint4*)(sWh + r1 * AST + c1 * 8) = pWh1;
        *(uint4*)(sWl + r0 * AST + c0 * 8) = pWl0;
        *(uint4*)(sWl + r1 * AST + c1 * 8) = pWl1;
        __syncthreads();

        if (kofs + KC < K) {
            const int kn = kofs + KC;
            pAh0 = *(const uint4*)(Ah + (size_t)(bm + r0) * K + kn + c0 * 8);
            pAh1 = *(const uint4*)(Ah + (size_t)(bm + r1) * K + kn + c1 * 8);
            pAl0 = *(const uint4*)(Al + (size_t)(bm + r0) * K + kn + c0 * 8);
            pAl1 = *(const uint4*)(Al + (size_t)(bm + r1) * K + kn + c1 * 8);
            pWh0 = *(const uint4*)(Wh + (size_t)(bn + r0) * K + kn + c0 * 8);
            pWh1 = *(const uint4*)(Wh + (size_t)(bn + r1) * K + kn + c1 * 8);
            pWl0 = *(const uint4*)(Wl + (size_t)(bn + r0) * K + kn + c0 * 8);
            pWl1 = *(const uint4*)(Wl + (size_t)(bn + r1) * K + kn + c1 * 8);
        }

        #pragma unroll
        for (int ks = 0; ks < KC / 16; ks++) {
            wmma::fragment<wmma::matrix_b, 16, 16, 16, __nv_bfloat16, wmma::col_major> b_hi[2], b_lo[2];
            #pragma unroll
            for (int j = 0; j < 2; j++) {
                wmma::load_matrix_sync(b_hi[j], &sWh[(wn * 32 + j * 16) * AST + ks * 16], AST);
                wmma::load_matrix_sync(b_lo[j], &sWl[(wn * 32 + j * 16) * AST + ks * 16], AST);
            }
            #pragma unroll
            for (int i = 0; i < 4; i++) {
                wmma::fragment<wmma::matrix_a, 16, 16, 16, __nv_bfloat16, wmma::row_major> a_hi, a_lo;
                wmma::load_matrix_sync(a_hi, &sAh[(wm * 64 + i * 16) * AST + ks * 16], AST);
                wmma::load_matrix_sync(a_lo, &sAl[(wm * 64 + i * 16) * AST + ks * 16], AST);
                #pragma unroll
                for (int j = 0; j < 2; j++) {
                    wmma::mma_sync(acc[i][j], a_hi, b_hi[j], acc[i][j]);
                    wmma::mma_sync(acc[i][j], a_hi, b_lo[j], acc[i][j]);
                    wmma::mma_sync(acc[i][j], a_lo, b_hi[j], acc[i][j]);
                }
            }
        }
        __syncthreads();
    }

    if (MODE == 1) {
        float* C = (z == 0) ? C0 : (z == 1) ? C1 : C2;
        #pragma unroll
        for (int i = 0; i < 4; i++)
            #pragma unroll
            for (int j = 0; j < 2; j++) {
                float* dst = C + (size_t)(bm + wm * 64 + i * 16) * N + bn + wn * 32 + j * 16;
                wmma::store_matrix_sync(dst, acc[i][j], N, wmma::mem_row_major);
            }
    } else {
        // bf16 hi/lo epilogue via per-warp smem scratch
        __nv_bfloat16* Chi = (z == 0) ? H0  : (z == 1) ? H1  : H2;
        __nv_bfloat16* Clo = (z == 0) ? Lo0 : (z == 1) ? Lo1 : Lo2;
        __syncthreads();                         // sA/sW frag reads done block-wide
        float* scratch = ((float*)sAh) + wid * 256;
        #pragma unroll
        for (int i = 0; i < 4; i++)
            #pragma unroll
            for (int j = 0; j < 2; j++) {
                wmma::store_matrix_sync(scratch, acc[i][j], 16, wmma::mem_row_major);
                __syncwarp();
                #pragma unroll
                for (int rb = 0; rb < 16; rb += 8) {
                    int rr = rb + (lane >> 2);
                    int cc = (lane & 3) * 4;
                    float4 vv = *(const float4*)(scratch + rr * 16 + cc);
                    size_t ofs = (size_t)(bm + wm * 64 + i * 16 + rr) * N + bn + wn * 32 + j * 16 + cc;
                    __nv_bfloat16 h0 = __float2bfloat16(vv.x);
                    __nv_bfloat16 h1 = __float2bfloat16(vv.y);
                    __nv_bfloat16 h2 = __float2bfloat16(vv.z);
                    __nv_bfloat16 h3 = __float2bfloat16(vv.w);
                    *(ushort4*)(Chi + ofs) = make_ushort4(
                        __bfloat16_as_ushort(h0), __bfloat16_as_ushort(h1),
                        __bfloat16_as_ushort(h2), __bfloat16_as_ushort(h3));
                    __nv_bfloat16 l0 = __float2bfloat16(vv.x - __bfloat162float(h0));
                    __nv_bfloat16 l1 = __float2bfloat16(vv.y - __bfloat162float(h1));
                    __nv_bfloat16 l2 = __float2bfloat16(vv.z - __bfloat162float(h2));
                    __nv_bfloat16 l3 = __float2bfloat16(vv.w - __bfloat162float(h3));
                    *(ushort4*)(Clo + ofs) = make_ushort4(
                        __bfloat16_as_ushort(l0), __bfloat16_as_ushort(l1),
                        __bfloat16_as_ushort(l2), __bfloat16_as_ushort(l3));
                }
                __syncwarp();
            }
    }
}

// ---------------------------------------------------------------------------
// Fused attention, tensor-core edition. Per block: 32 queries x 1024 keys,
// one (b,h). S = QK^T via 3-term wmma -> softmax (scale+mask folded) ->
// attn write -> PV via 3-term wmma (P split per chunk) -> ctx bf16 hi/lo.
// ---------------------------------------------------------------------------
#define QT 32
#define SQK 72     // bf16 row stride for Q/K/V tiles (144B rows, 16B-aligned, mult of 8)
#define PST 1032   // fp32 score stride (mult of 4, rows 16B-aligned)
#define PCH 136    // bf16 P-chunk stride (272B rows, 16B-aligned, mult of 8)

// smem byte offsets
#define FA_QH 0
#define FA_QL (FA_QH + QT*SQK*2)              // 4608
#define FA_KH (FA_QL + QT*SQK*2)              // 9216
#define FA_KL (FA_KH + 128*SQK*2)             // 27648
#define FA_PH (FA_KL + 128*SQK*2)             // 46080
#define FA_PL (FA_PH + QT*PCH*2)              // 54784
#define FA_PS (FA_PL + QT*PCH*2)              // 63488 (16B aligned)
#define SMEM_FA (FA_PS + QT*PST*4)            // 195584 B

__global__ __launch_bounds__(256)
void fused_attn_wmma(const __nv_bfloat16* __restrict__ qhi, const __nv_bfloat16* __restrict__ qlo,
                     const __nv_bfloat16* __restrict__ khi, const __nv_bfloat16* __restrict__ klo,
                     const __nv_bfloat16* __restrict__ vhi, const __nv_bfloat16* __restrict__ vlo,
                     const int* __restrict__ seq_len,
                     float* __restrict__ attn,
                     __nv_bfloat16* __restrict__ ctx_hi, __nv_bfloat16* __restrict__ ctx_lo)
{
    extern __shared__ char smem[];
    __nv_bfloat16* Qh = (__nv_bfloat16*)(smem + FA_QH);
    __nv_bfloat16* Ql = (__nv_bfloat16*)(smem + FA_QL);
    __nv_bfloat16* Kh = (__nv_bfloat16*)(smem + FA_KH);   // reused for V in phase 4
    __nv_bfloat16* Kl = (__nv_bfloat16*)(smem + FA_KL);
    __nv_bfloat16* Ph = (__nv_bfloat16*)(smem + FA_PH);
    __nv_bfloat16* Pl = (__nv_bfloat16*)(smem + FA_PL);
    float*         Ps = (float*)(smem + FA_PS);

    const int t    = threadIdx.x;
    const int wid  = t >> 5;
    const int lane = t & 31;
    const int q0   = blockIdx.x * QT;
    const int bh   = blockIdx.y;
    const int b    = bh / NH;
    const int h    = bh % NH;
    const int sl   = seq_len[b];

    const size_t headbase = (size_t)b * LL * DD + h * DK;

    // ---- load Q tile [32][64] hi/lo: 256 16B-chunks each, 1/thread ----
    {
        int r = t >> 3, c = t & 7;
        size_t src = headbase + (size_t)(q0 + r) * DD + c * 8;
        *(uint4*)(Qh + r * SQK + c * 8) = *(const uint4*)(qhi + src);
        *(uint4*)(Ql + r * SQK + c * 8) = *(const uint4*)(qlo + src);
    }

    // ---- Phase 1: S = Q K^T via wmma, tiles of 128 keys ----
    uint4 pf_h[4], pf_l[4];
    #pragma unroll
    for (int i = 0; i < 4; i++) {
        int ci = t + i * 256, r = ci >> 3, c = ci & 7;
        size_t src = headbase + (size_t)r * DD + c * 8;
        pf_h[i] = *(const uint4*)(khi + src);
        pf_l[i] = *(const uint4*)(klo + src);
    }

    for (int kt = 0; kt < LL; kt += 128) {
        __syncthreads();
        #pragma unroll
        for (int i = 0; i < 4; i++) {
            int ci = t + i * 256, r = ci >> 3, c = ci & 7;
            *(uint4*)(Kh + r * SQK + c * 8) = pf_h[i];
            *(uint4*)(Kl + r * SQK + c * 8) = pf_l[i];
        }
        if (kt + 128 < LL) {
            #pragma unroll
            for (int i = 0; i < 4; i++) {
                int ci = t + i * 256, r = ci >> 3, c = ci & 7;
                size_t src = headbase + (size_t)(kt + 128 + r) * DD + c * 8;
                pf_h[i] = *(const uint4*)(khi + src);
                pf_l[i] = *(const uint4*)(klo + src);
            }
        }
        __syncthreads();

        wmma::fragment<wmma::accumulator, 16, 16, 16, float> sacc[2];
        wmma::fill_fragment(sacc[0], 0.0f);
        wmma::fill_fragment(sacc[1], 0.0f);
        #pragma unroll
        for (int ks = 0; ks < 4; ks++) {
            wmma::fragment<wmma::matrix_b, 16, 16, 16, __nv_bfloat16, wmma::col_major> kb_h, kb_l;
            wmma::load_matrix_sync(kb_h, Kh + (wid * 16) * SQK + ks * 16, SQK);
            wmma::load_matrix_sync(kb_l, Kl + (wid * 16) * SQK + ks * 16, SQK);
            #pragma unroll
            for (int m = 0; m < 2; m++) {
                wmma::fragment<wmma::matrix_a, 16, 16, 16, __nv_bfloat16, wmma::row_major> qa_h, qa_l;
                wmma::load_matrix_sync(qa_h, Qh + (m * 16) * SQK + ks * 16, SQK);
                wmma::load_matrix_sync(qa_l, Ql + (m * 16) * SQK + ks * 16, SQK);
                wmma::mma_sync(sacc[m], qa_h, kb_h, sacc[m]);
                wmma::mma_sync(sacc[m], qa_h, kb_l, sacc[m]);
                wmma::mma_sync(sacc[m], qa_l, kb_h, sacc[m]);
            }
        }
        #pragma unroll
        for (int m = 0; m < 2; m++)
            wmma::store_matrix_sync(Ps + (m * 16) * PST + kt + wid * 16, sacc[m], PST,
                                    wmma::mem_row_major);
    }
    __syncthreads();

    // ---- Phase 2: softmax with scale (1/8) + key mask folded in ----
    {
        const int g    = t >> 3;
        const int su   = t & 7;
        const bool live = (q0 + g) < sl;
        float* row = Ps + g * PST;

        float mx = -INFINITY;
        #pragma unroll 16
        for (int m = 0; m < 128; m++) {
            int kk = su + m * 8;
            float v = (kk < sl) ? row[kk] * 0.125f : -INFINITY;
            mx = fmaxf(mx, v);
        }
        #pragma unroll
        for (int o = 4; o > 0; o >>= 1) mx = fmaxf(mx, __shfl_xor_sync(0xffffffffu, mx, o, 8));

        float s = 0.0f;
        #pragma unroll 16
        for (int m = 0; m < 128; m++) {
            int kk = su + m * 8;
            float v = (kk < sl) ? row[kk] * 0.125f : -INFINITY;
            float ev = __expf(v - mx);
            row[kk] = ev;
            s += ev;
        }
        #pragma unroll
        for (int o = 4; o > 0; o >>= 1) s += __shfl_xor_sync(0xffffffffu, s, o, 8);

        const float inv = live ? (1.0f / s) : 0.0f;
        #pragma unroll 16
        for (int m = 0; m < 128; m++) row[su + m * 8] *= inv;
    }
    __syncthreads();

    // ---- Phase 3: write attention probs (single mandatory pass) ----
    {
        float* ab = attn + ((size_t)(h * BB + b)) * LL * LL + (size_t)q0 * LL;
        #pragma unroll
        for (int m = 0; m < 32; m++) {
            int fi = m * 256 + t;
            int r  = fi >> 8;
            int c4 = fi & 255;
            const float* src = Ps + r * PST + c4 * 4;
            *(float4*)(ab + (size_t)r * LL + c4 * 4) =
                make_float4(src[0], src[1], src[2], src[3]);
        }
    }

    // ---- Phase 4: ctx = P @ V via wmma, 128-key chunks ----
    const int pm = wid >> 2;     // 0..1: query rows
    const int pn = wid & 3;      // 0..3: dv cols
    wmma::fragment<wmma::accumulator, 16, 16, 16, float> pacc;
    wmma::fill_fragment(pacc, 0.0f);

    #pragma unroll
    for (int i = 0; i < 4; i++) {
        int ci = t + i * 256, r = ci >> 3, c = ci & 7;
        size_t src = headbase + (size_t)r * DD + c * 8;
        pf_h[i] = *(const uint4*)(vhi + src);
        pf_l[i] = *(const uint4*)(vlo + src);
    }

    for (int kc = 0; kc < 8; kc++) {
        __syncthreads();
        #pragma unroll
        for (int i = 0; i < 4; i++) {
            int ci = t + i * 256, r = ci >> 3, c = ci & 7;
            *(uint4*)(Kh + r * SQK + c * 8) = pf_h[i];
            *(uint4*)(Kl + r * SQK + c * 8) = pf_l[i];
        }
        if (kc + 1 < 8) {
            #pragma unroll
            for (int i = 0; i < 4; i++) {
                int ci = t + i * 256, r = ci >> 3, c = ci & 7;
                size_t src = headbase + (size_t)((kc + 1) * 128 + r) * DD + c * 8;
                pf_h[i] = *(const uint4*)(vhi + src);
                pf_l[i] = *(const uint4*)(vlo + src);
            }
        }
        // convert P chunk [32][128] fp32 -> bf16 hi/lo
        #pragma unroll
        for (int i = 0; i < 4; i++) {
            int c = t + i * 256;
            int r = c >> 5, c4 = c & 31;
            float4 pv = *(const float4*)(Ps + r * PST + kc * 128 + c4 * 4);
            __nv_bfloat16 h0 = __float2bfloat16(pv.x);
            __nv_bfloat16 h1 = __float2bfloat16(pv.y);
            __nv_bfloat16 h2 = __float2bfloat16(pv.z);
            __nv_bfloat16 h3 = __float2bfloat16(pv.w);
            *(ushort4*)(Ph + r * PCH + c4 * 4) = make_ushort4(
                __bfloat16_as_ushort(h0), __bfloat16_as_ushort(h1),
                __bfloat16_as_ushort(h2), __bfloat16_as_ushort(h3));
            __nv_bfloat16 l0 = __float2bfloat16(pv.x - __bfloat162float(h0));
            __nv_bfloat16 l1 = __float2bfloat16(pv.y - __bfloat162float(h1));
            __nv_bfloat16 l2 = __float2bfloat16(pv.z - __bfloat162float(h2));
            __nv_bfloat16 l3 = __float2bfloat16(pv.w - __bfloat162float(h3));
            *(ushort4*)(Pl + r * PCH + c4 * 4) = make_ushort4(
                __bfloat16_as_ushort(l0), __bfloat16_as_ushort(l1),
                __bfloat16_as_ushort(l2), __bfloat16_as_ushort(l3));
        }
        __syncthreads();

        #pragma unroll
        for (int ks = 0; ks < 8; ks++) {
            wmma::fragment<wmma::matrix_a, 16, 16, 16, __nv_bfloat16, wmma::row_major> pa_h, pa_l;
            wmma::fragment<wmma::matrix_b, 16, 16, 16, __nv_bfloat16, wmma::row_major> vb_h, vb_l;
            wmma::load_matrix_sync(pa_h, Ph + (pm * 16) * PCH + ks * 16, PCH);
            wmma::load_matrix_sync(pa_l, Pl + (pm * 16) * PCH + ks * 16, PCH);
            wmma::load_matrix_sync(vb_h, Kh + (ks * 16) * SQK + pn * 16, SQK);
            wmma::load_matrix_sync(vb_l, Kl + (ks * 16) * SQK + pn * 16, SQK);
            wmma::mma_sync(pacc, pa_h, vb_h, pacc);
            wmma::mma_sync(pacc, pa_h, vb_l, pacc);
            wmma::mma_sync(pacc, pa_l, vb_h, pacc);
        }
    }

    // ---- epilogue: ctx tile -> bf16 hi/lo (per-warp scratch in Qh region) ----
    {
        float* scratch = ((float*)(smem + FA_QH)) + wid * 256;   // 8KB total, Q dead
        __syncthreads();
        wmma::store_matrix_sync(scratch, pacc, 16, wmma::mem_row_major);
        __syncwarp();
        #pragma unroll
        for (int rb = 0; rb < 16; rb += 8) {
            int rr = rb + (lane >> 2);
            int cc = (lane & 3) * 4;
            float4 vv = *(const float4*)(scratch + rr * 16 + cc);
            size_t ofs = headbase + (size_t)(q0 + pm * 16 + rr) * DD + pn * 16 + cc;
            __nv_bfloat16 h0 = __float2bfloat16(vv.x);
            __nv_bfloat16 h1 = __float2bfloat16(vv.y);
            __nv_bfloat16 h2 = __float2bfloat16(vv.z);
            __nv_bfloat16 h3 = __float2bfloat16(vv.w);
            *(ushort4*)(ctx_hi + ofs) = make_ushort4(
                __bfloat16_as_ushort(h0), __bfloat16_as_ushort(h1),
                __bfloat16_as_ushort(h2), __bfloat16_as_ushort(h3));
            __nv_bfloat16 l0 = __float2bfloat16(vv.x - __bfloat162float(h0));
            __nv_bfloat16 l1 = __float2bfloat16(vv.y - __bfloat162float(h1));
            __nv_bfloat16 l2 = __float2bfloat16(vv.z - __bfloat162float(h2));
            __nv_bfloat16 l3 = __float2bfloat16(vv.w - __bfloat162float(h3));
            *(ushort4*)(ctx_lo + ofs) = make_ushort4(
                __bfloat16_as_ushort(l0), __bfloat16_as_ushort(l1),
                __bfloat16_as_ushort(l2), __bfloat16_as_ushort(l3));
        }
    }
}

// ---------------------------------------------------------------------------
__device__ __forceinline__ float block_reduce_sum(float v)
{
    __shared__ float sh[8];
    int lane = threadIdx.x & 31, w = threadIdx.x >> 5;
    #pragma unroll
    for (int o = 16; o > 0; o >>= 1) v += __shfl_xor_sync(0xffffffffu, v, o);
    if (lane == 0) sh[w] = v;
    __syncthreads();
    if (w == 0) {
        float x = (lane < 8) ? sh[lane] : 0.0f;
        #pragma unroll
        for (int o = 4; o > 0; o >>= 1) x += __shfl_xor_sync(0xffffffffu, x, o);
        if (lane == 0) sh[0] = x;
    }
    __syncthreads();
    float r = sh[0];
    __syncthreads();
    return r;
}

// LayerNorm per row, residual folded: out = LN(x + res).
__global__ __launch_bounds__(256)
void layernorm_kernel(const float* __restrict__ x, const float* __restrict__ res,
                      const float* __restrict__ gamma, const float* __restrict__ beta,
                      float* __restrict__ out)
{
    const int row = blockIdx.x;
    const float* xr = x   + (size_t)row * DD;
    const float* rr = res + (size_t)row * DD;
    const int t = threadIdx.x;

    float v[4], s = 0.0f;
    #pragma unroll
    for (int i = 0; i < 4; i++) {
        int c = t + i * 256;
        v[i] = xr[c] + rr[c];
        s += v[i];
    }
    s = block_reduce_sum(s);
    const float mu = s * (1.0f / DD);

    float s2 = 0.0f;
    #pragma unroll
    for (int i = 0; i < 4; i++) { float d = v[i] - mu; s2 += d * d; }
    s2 = block_reduce_sum(s2);
    const float inv = rsqrtf(s2 * (1.0f / DD) + LN_EPS);

    #pragma unroll
    for (int i = 0; i < 4; i++) {
        int c = t + i * 256;
        out[(size_t)row * DD + c] = (v[i] - mu) * inv * gamma[c] + beta[c];
    }
}

// ---------------------------------------------------------------------------
// Launch
// ---------------------------------------------------------------------------
extern "C" void kernel_launch(void* const* d_in, const int* in_sizes, int n_in,
                              void* d_out, int out_size)
{
    const float* q       = (const float*)d_in[0];
    const float* k       = (const float*)d_in[1];
    const float* v       = (const float*)d_in[2];
    const int*   seq_len = (const int*)  d_in[3];
    const float* w_qs    = (const float*)d_in[4];
    const float* b_qs    = (const float*)d_in[5];
    const float* w_ks    = (const float*)d_in[6];
    const float* b_ks    = (const float*)d_in[7];
    const float* w_vs    = (const float*)d_in[8];
    const float* b_vs    = (const float*)d_in[9];
    const float* fc_w    = (const float*)d_in[10];
    const float* fc_b    = (const float*)d_in[11];
    const float* ln_g    = (const float*)d_in[12];
    const float* ln_b    = (const float*)d_in[13];

    float* out  = (float*)d_out;
    float* attn = out + (size_t)BB * LL * DD;

    __nv_bfloat16 *ahi, *alo, *whi, *wlo, *phi, *plo, *chi, *clo;
    float* x2;
    cudaGetSymbolAddress((void**)&ahi, g_act_hi);
    cudaGetSymbolAddress((void**)&alo, g_act_lo);
    cudaGetSymbolAddress((void**)&whi, g_w_hi);
    cudaGetSymbolAddress((void**)&wlo, g_w_lo);
    cudaGetSymbolAddress((void**)&phi, g_proj_hi);
    cudaGetSymbolAddress((void**)&plo, g_proj_lo);
    cudaGetSymbolAddress((void**)&chi, g_ctx_hi);
    cudaGetSymbolAddress((void**)&clo, g_ctx_lo);
    cudaGetSymbolAddress((void**)&x2,  g_x2);

    cudaFuncSetAttribute(fused_attn_wmma,
                         cudaFuncAttributeMaxDynamicSharedMemorySize, SMEM_FA);

    const int M = BB * LL;
    const int ACT4 = SA / 4;
    const int W4   = SW / 4;

    // converts: 2 batched launches
    cvt_splitN<<<dim3(ACT4 / 256, 1, 3), 256>>>(q, k, v, q, ahi, alo, (size_t)SA, ACT4);
    cvt_splitN<<<dim3(W4 / 256, 1, 4), 256>>>(w_qs, w_ks, w_vs, fc_w, whi, wlo, (size_t)SW, W4);

    // QKV projections -> bf16 hi/lo (bias included)
    wgemm128<0><<<dim3(DD / 128, M / 128, 3), 256>>>(
        ahi, alo, whi, wlo, b_qs, b_ks, b_vs,
        nullptr, nullptr, nullptr,
        phi + 0*(size_t)SA, phi + 1*(size_t)SA, phi + 2*(size_t)SA,
        plo + 0*(size_t)SA, plo + 1*(size_t)SA, plo + 2*(size_t)SA,
        M, DD, DD, (size_t)SA, (size_t)SW);

    fused_attn_wmma<<<dim3(LL / QT, BB * NH), 256, SMEM_FA>>>(
        phi + 0*(size_t)SA, plo + 0*(size_t)SA,
        phi + 1*(size_t)SA, plo + 1*(size_t)SA,
        phi + 2*(size_t)SA, plo + 2*(size_t)SA,
        seq_len, attn, chi, clo);

    // FC: ctx @ fc_w^T + fc_b -> fp32 (residual folds into LN)
    wgemm128<1><<<dim3(DD / 128, M / 128, 1), 256>>>(
        chi, clo, whi + 3*(size_t)SW, wlo + 3*(size_t)SW,
        fc_b, fc_b, fc_b,
        x2, x2, x2,
        nullptr, nullptr, nullptr, nullptr, nullptr, nullptr,
        M, DD, DD, 0, 0);

    layernorm_kernel<<<M, 256>>>(x2, q, ln_g, ln_b, out);
}